// round 12
// baseline (speedup 1.0000x reference)
#include <cuda_runtime.h>
#include <math.h>
#include <stdint.h>

// IAF, 2 MADE flows, B=4096, D=H=64.
// Identity (verified R1/R4-R11): the reference forward scan is the exact
// inverse of z -> z - shift(z), so density = -0.5*D*log(2pi) - 0.5*sum(lv)
// - 0.5*sum(eps^2); only the inverse pass (8 masked [Bx64]@[64x64] GEMMs) runs.
// R12: single kernel, smem-staged masked weights (row-major padded).
// Mainloop: 16 warps = 2 tiles x 8 n-blocks, tile-scoped named barriers,
// B-fragment LDS double-buffered, dual MMA accumulator chains, flow reversal
// folded into layer-4 A indexing (no reversal barriers), register biases.

#define C_DENS (-58.81206612509905f)
#define AST 68                 // padded row stride (floats)
#define WST (64 * AST)         // floats per staged matrix (4352)

static __device__ __forceinline__ void mma8(float* d, const float* a, float2 b) {
    asm volatile(
        "mma.sync.aligned.m16n8k8.row.col.f32.tf32.tf32.f32 "
        "{%0,%1,%2,%3}, {%4,%5,%6,%7}, {%8,%9}, {%0,%1,%2,%3};"
        : "+f"(d[0]), "+f"(d[1]), "+f"(d[2]), "+f"(d[3])
        : "r"(__float_as_uint(a[0])), "r"(__float_as_uint(a[1])),
          "r"(__float_as_uint(a[2])), "r"(__float_as_uint(a[3])),
          "r"(__float_as_uint(b.x)), "r"(__float_as_uint(b.y)));
}

static __device__ __forceinline__ void tile_bar(int p) {
    asm volatile("bar.sync %0, 256;" :: "r"(p + 1) : "memory");
}

__global__ __launch_bounds__(512, 1)
void iaf_main(const float* __restrict__ zm, const float* __restrict__ lv,
              const float* __restrict__ ep,
              const float* __restrict__ W0, const float* __restrict__ b0,
              const float* __restrict__ W1, const float* __restrict__ b1,
              const float* __restrict__ W2, const float* __restrict__ b2,
              const float* __restrict__ Wo, const float* __restrict__ bo,
              float* __restrict__ out, int B)
{
    extern __shared__ float sm[];
    float* wsm  = sm;                         // [8][64][AST] masked weights
    float* actb = wsm + 8 * WST;              // [2][2][16][AST] ping-pong acts
    float* zb   = actb + 2 * 2 * 16 * AST;    // [2][16][AST] z (u after flow 1)

    const int t = threadIdx.x;
    const int lane = t & 31, wid = t >> 5;
    const int p = wid >> 3, h = wid & 7;      // tile, n-block (8 cols)
    const int g = lane >> 2, tig = lane & 3;
    const int rowbase = blockIdx.x * 32 + p * 16;
    const int n = h * 8 + g;                  // this lane's weight column
    const int c = 8 * h + 2 * tig;            // this lane's output column pair

    // ---- Preamble: stage masked weights (coalesced LDG, float4 STS).
    // d_h[h] = h % 63 + 1. Masks: m_in: k <= n%63 ; m_hid: k%63 <= n%63 ;
    // m_out: k%63 < n.  mat = f*4 + l.
    #pragma unroll
    for (int it = 0; it < 16; ++it) {
        int i   = t + it * 512;               // float4 granule, 0..8191
        int mat = i >> 10;
        int f = mat >> 2, l = mat & 3;
        int e  = (i & 1023) << 2;
        int k  = e >> 6, n0 = e & 63;
        const float* src = (l == 0) ? W0 : (l == 1) ? W1 : (l == 2) ? W2 : Wo;
        float4 w = *(const float4*)(src + f * 4096 + k * 64 + n0);
        int km = (k == 63) ? 0 : k;           // k % 63
        float vals[4] = {w.x, w.y, w.z, w.w};
        #pragma unroll
        for (int q = 0; q < 4; ++q) {
            int nn = n0 + q;
            int nm = (nn == 63) ? 0 : nn;
            bool keep = (l == 0) ? (k <= nm)
                      : (l == 3) ? (km < nn)
                                 : (km <= nm);
            if (!keep) vals[q] = 0.0f;
        }
        *(float4*)(wsm + mat * WST + k * AST + n0) =
            make_float4(vals[0], vals[1], vals[2], vals[3]);
    }

    // Biases for this lane's columns, all 8 layers (exec order), registers.
    float2 biasr[8];
    {
        const float* Bseq[8] = { b0 + 64, b1 + 64, b2 + 64, bo + 64,
                                 b0,      b1,      b2,      bo      };
        #pragma unroll
        for (int i = 0; i < 8; ++i)
            biasr[i] = *(const float2*)(Bseq[i] + c);
    }

    // ---- Init: z0 = zm + exp(0.5*lv)*eps; density.
    {
        int r = t >> 4, seg = t & 15;         // 32 rows x 16 col-segments
        int pi = r >> 4, ri = r & 15;
        int gr = blockIdx.x * 32 + r;
        bool v = gr < B;
        int col = seg * 4;
        const size_t go = (size_t)gr * 64 + col;
        float4 a = v ? *(const float4*)(zm + go) : make_float4(0,0,0,0);
        float4 b = v ? *(const float4*)(lv + go) : make_float4(0,0,0,0);
        float4 cc = v ? *(const float4*)(ep + go) : make_float4(0,0,0,0);
        float4 z4;
        z4.x = a.x + __expf(0.5f * b.x) * cc.x;
        z4.y = a.y + __expf(0.5f * b.y) * cc.y;
        z4.z = a.z + __expf(0.5f * b.z) * cc.z;
        z4.w = a.w + __expf(0.5f * b.w) * cc.w;
        *(float4*)(actb + ((0 * 2 + pi) * 16 + ri) * AST + col) = z4;
        *(float4*)(zb   + (pi * 16 + ri) * AST + col)           = z4;
        float slv = b.x + b.y + b.z + b.w;
        float se2 = cc.x*cc.x + cc.y*cc.y + cc.z*cc.z + cc.w*cc.w;
        #pragma unroll
        for (int m = 1; m <= 8; m <<= 1) {
            slv += __shfl_xor_sync(0xffffffffu, slv, m);
            se2 += __shfl_xor_sync(0xffffffffu, se2, m);
        }
        if (seg == 0 && v)
            out[(size_t)B * 64 + gr] = C_DENS - 0.5f * slv - 0.5f * se2;
    }
    __syncthreads();

    float* zrow0 = zb + (p * 16 + g) * AST;
    float* zrow1 = zb + (p * 16 + g + 8) * AST;

    // Prefetch layer-0 B-fragments (mat exec order: 4,5,6,7,0,1,2,3).
    float2 Bcur[8], Bnxt[8];
    {
        const float* wb = wsm + 4 * WST + n;
        #pragma unroll
        for (int kb = 0; kb < 8; ++kb) {
            int k0 = kb * 8 + tig;
            Bcur[kb] = make_float2(wb[k0 * AST], wb[(k0 + 4) * AST]);
        }
    }

    // ---- 8 chained layers, fully unrolled; tile-scoped barriers.
    // Flow reversal folded into layer-4 A reads (columns 63-k) and the final
    // epilogue's swapped zbuf read; zbuf always stores u (unreversed).
    #pragma unroll
    for (int li = 0; li < 8; ++li) {
        const int l  = ((li < 4) ? (4 + li) : (li - 4)) & 3;
        const int rd = li & 1, wr = (li + 1) & 1;

        // Prefetch next layer's B-fragments (overlaps this layer's MMAs).
        if (li < 7) {
            const int nmat = (li < 3) ? (5 + li) : (li - 3);
            const float* wb = wsm + nmat * WST + n;
            #pragma unroll
            for (int kb = 0; kb < 8; ++kb) {
                int k0 = kb * 8 + tig;
                Bnxt[kb] = make_float2(wb[k0 * AST], wb[(k0 + 4) * AST]);
            }
        }

        // A-fragments (conflict-free LDS; layer 4 reads reversed columns).
        const float* ar0 = actb + ((rd * 2 + p) * 16 + g) * AST;
        const float* ar1 = actb + ((rd * 2 + p) * 16 + g + 8) * AST;
        float Afr[32];
        #pragma unroll
        for (int kb = 0; kb < 8; ++kb) {
            int k0 = kb * 8 + tig, k1 = k0 + 4;
            if (li == 4) { k0 = 63 - k0; k1 = 63 - k1; }
            Afr[kb*4+0] = ar0[k0];
            Afr[kb*4+1] = ar1[k0];
            Afr[kb*4+2] = ar0[k1];
            Afr[kb*4+3] = ar1[k1];
        }

        // Dual accumulator chains, merged at the end.
        float accA[4] = {0.f, 0.f, 0.f, 0.f};
        float accB[4] = {0.f, 0.f, 0.f, 0.f};
        #pragma unroll
        for (int kb = 0; kb < 4; ++kb) mma8(accA, Afr + kb*4, Bcur[kb]);
        #pragma unroll
        for (int kb = 4; kb < 8; ++kb) mma8(accB, Afr + kb*4, Bcur[kb]);
        float acc[4];
        #pragma unroll
        for (int i = 0; i < 4; ++i) acc[i] = accA[i] + accB[i];

        const float2 bias = biasr[li];
        float* aw0 = actb + ((wr * 2 + p) * 16 + g) * AST;
        float* aw1 = actb + ((wr * 2 + p) * 16 + g + 8) * AST;

        if (l < 3) {
            float v0 = fmaxf(acc[0] + bias.x, 0.f);
            float v1 = fmaxf(acc[1] + bias.y, 0.f);
            float v2 = fmaxf(acc[2] + bias.x, 0.f);
            float v3 = fmaxf(acc[3] + bias.y, 0.f);
            *(float2*)(aw0 + c) = make_float2(v0, v1);
            *(float2*)(aw1 + c) = make_float2(v2, v3);
            tile_bar(p);
        } else if (li == 3) {
            // u = z - shift_1(z); store u unreversed (same-lane zbuf rmw).
            float2 z0 = *(const float2*)(zrow0 + c);
            float2 z1 = *(const float2*)(zrow1 + c);
            float u0 = z0.x - (acc[0] + bias.x);
            float u1 = z0.y - (acc[1] + bias.y);
            float u2 = z1.x - (acc[2] + bias.x);
            float u3 = z1.y - (acc[3] + bias.y);
            *(float2*)(aw0 + c) = make_float2(u0, u1);
            *(float2*)(aw1 + c) = make_float2(u2, u3);
            *(float2*)(zrow0 + c) = make_float2(u0, u1);
            *(float2*)(zrow1 + c) = make_float2(u2, u3);
            tile_bar(p);
        } else {
            // Final: out[c] = v[c] - shift_0(v)[c], v[c] = u[63-c].
            float2 zr0 = *(const float2*)(zrow0 + 62 - c);  // (u[62-c], u[63-c])
            float2 zr1 = *(const float2*)(zrow1 + 62 - c);
            float zn0 = zr0.y - (acc[0] + bias.x);
            float zn1 = zr0.x - (acc[1] + bias.y);
            float zn2 = zr1.y - (acc[2] + bias.x);
            float zn3 = zr1.x - (acc[3] + bias.y);
            const int r0 = rowbase + g, r1 = r0 + 8;
            if (r0 < B)
                *(float2*)(out + (size_t)r0*64 + c) = make_float2(zn0, zn1);
            if (r1 < B)
                *(float2*)(out + (size_t)r1*64 + c) = make_float2(zn2, zn3);
        }

        // Rotate prefetch buffer (register renames under full unroll).
        #pragma unroll
        for (int i = 0; i < 8; ++i) Bcur[i] = Bnxt[i];
    }
}

extern "C" void kernel_launch(void* const* d_in, const int* in_sizes, int n_in,
                              void* d_out, int out_size) {
    const float* zm = (const float*)d_in[0];
    const float* lv = (const float*)d_in[1];
    const float* ep = (const float*)d_in[2];
    const float* W0 = (const float*)d_in[3];
    const float* b0 = (const float*)d_in[4];
    const float* W1 = (const float*)d_in[5];
    const float* b1 = (const float*)d_in[6];
    const float* W2 = (const float*)d_in[7];
    const float* b2 = (const float*)d_in[8];
    const float* Wo = (const float*)d_in[9];
    const float* bo = (const float*)d_in[10];

    int B = in_sizes[0] / 64;

    int smem = (8 * WST + 2 * 2 * 16 * AST + 2 * 16 * AST) * (int)sizeof(float);
    cudaFuncSetAttribute(iaf_main, cudaFuncAttributeMaxDynamicSharedMemorySize,
                         smem);
    int grid = (B + 31) / 32;
    iaf_main<<<grid, 512, smem>>>(zm, lv, ep, W0, b0, W1, b1, W2, b2, Wo, bo,
                                  (float*)d_out, B);
}

// round 13
// speedup vs baseline: 1.1465x; 1.1465x over previous
#include <cuda_runtime.h>
#include <math.h>
#include <stdint.h>

// IAF, 2 MADE flows, B=4096, D=H=64.
// Identity (verified R1/R4-R12): the reference forward scan is the exact
// inverse of z -> z - shift(z), so density = -0.5*D*log(2pi) - 0.5*sum(lv)
// - 0.5*sum(eps^2); only the inverse pass (8 masked [Bx64]@[64x64] GEMMs) runs.
// R13: weight smem row stride 72 -> B-fragment LDS bank-conflict-free
// (bank = 8*((tig+h)&3)+g, all lanes distinct); weight LDGs issued before
// init so the L2 window overlaps init; otherwise R12 structure (16 warps =
// 2 tiles x 8 n-blocks, tile barriers, folded reversal, register biases).

#define C_DENS (-58.81206612509905f)
#define AST  68                // activation row stride (floats)
#define WROW 72                // weight row stride (floats) -> conflict-free B
#define WST  (64 * WROW)       // floats per staged matrix (4608)

static __device__ __forceinline__ void mma8(float* d, const float* a, float2 b) {
    asm volatile(
        "mma.sync.aligned.m16n8k8.row.col.f32.tf32.tf32.f32 "
        "{%0,%1,%2,%3}, {%4,%5,%6,%7}, {%8,%9}, {%0,%1,%2,%3};"
        : "+f"(d[0]), "+f"(d[1]), "+f"(d[2]), "+f"(d[3])
        : "r"(__float_as_uint(a[0])), "r"(__float_as_uint(a[1])),
          "r"(__float_as_uint(a[2])), "r"(__float_as_uint(a[3])),
          "r"(__float_as_uint(b.x)), "r"(__float_as_uint(b.y)));
}

static __device__ __forceinline__ void tile_bar(int p) {
    asm volatile("bar.sync %0, 256;" :: "r"(p + 1) : "memory");
}

__global__ __launch_bounds__(512, 1)
void iaf_main(const float* __restrict__ zm, const float* __restrict__ lv,
              const float* __restrict__ ep,
              const float* __restrict__ W0, const float* __restrict__ b0,
              const float* __restrict__ W1, const float* __restrict__ b1,
              const float* __restrict__ W2, const float* __restrict__ b2,
              const float* __restrict__ Wo, const float* __restrict__ bo,
              float* __restrict__ out, int B)
{
    extern __shared__ float sm[];
    float* wsm  = sm;                         // [8][64][WROW] masked weights
    float* actb = wsm + 8 * WST;              // [2][2][16][AST] ping-pong acts
    float* zb   = actb + 2 * 2 * 16 * AST;    // [2][16][AST] z (u after flow 1)

    const int t = threadIdx.x;
    const int lane = t & 31, wid = t >> 5;
    const int p = wid >> 3, h = wid & 7;      // tile, n-block (8 cols)
    const int g = lane >> 2, tig = lane & 3;
    const int rowbase = blockIdx.x * 32 + p * 16;
    const int n = h * 8 + g;                  // this lane's weight column
    const int c = 8 * h + 2 * tig;            // this lane's output column pair

    // ---- Issue ALL weight LDGs first; latency overlaps init below.
    float4 wv[16];
    #pragma unroll
    for (int it = 0; it < 16; ++it) {
        int i   = t + it * 512;               // float4 granule, 0..8191
        int mat = i >> 10;
        int f = mat >> 2, l = mat & 3;
        int e = (i & 1023) << 2;
        const float* src = (l == 0) ? W0 : (l == 1) ? W1 : (l == 2) ? W2 : Wo;
        wv[it] = *(const float4*)(src + f * 4096 + e);
    }

    // Biases for this lane's columns, all 8 layers (exec order), registers.
    float2 biasr[8];
    {
        const float* Bseq[8] = { b0 + 64, b1 + 64, b2 + 64, bo + 64,
                                 b0,      b1,      b2,      bo      };
        #pragma unroll
        for (int i = 0; i < 8; ++i)
            biasr[i] = *(const float2*)(Bseq[i] + c);
    }

    // ---- Init: z0 = zm + exp(0.5*lv)*eps; density.
    {
        int r = t >> 4, seg = t & 15;         // 32 rows x 16 col-segments
        int pi = r >> 4, ri = r & 15;
        int gr = blockIdx.x * 32 + r;
        bool v = gr < B;
        int col = seg * 4;
        const size_t go = (size_t)gr * 64 + col;
        float4 a = v ? *(const float4*)(zm + go) : make_float4(0,0,0,0);
        float4 b = v ? *(const float4*)(lv + go) : make_float4(0,0,0,0);
        float4 cc = v ? *(const float4*)(ep + go) : make_float4(0,0,0,0);
        float4 z4;
        z4.x = a.x + __expf(0.5f * b.x) * cc.x;
        z4.y = a.y + __expf(0.5f * b.y) * cc.y;
        z4.z = a.z + __expf(0.5f * b.z) * cc.z;
        z4.w = a.w + __expf(0.5f * b.w) * cc.w;
        *(float4*)(actb + ((0 * 2 + pi) * 16 + ri) * AST + col) = z4;
        *(float4*)(zb   + (pi * 16 + ri) * AST + col)           = z4;
        float slv = b.x + b.y + b.z + b.w;
        float se2 = cc.x*cc.x + cc.y*cc.y + cc.z*cc.z + cc.w*cc.w;
        #pragma unroll
        for (int m = 1; m <= 8; m <<= 1) {
            slv += __shfl_xor_sync(0xffffffffu, slv, m);
            se2 += __shfl_xor_sync(0xffffffffu, se2, m);
        }
        if (seg == 0 && v)
            out[(size_t)B * 64 + gr] = C_DENS - 0.5f * slv - 0.5f * se2;
    }

    // ---- Mask + store staged weights.
    // d_h[h] = h % 63 + 1. Masks: m_in: k <= n%63 ; m_hid: k%63 <= n%63 ;
    // m_out: k%63 < n.  mat = f*4 + l.
    #pragma unroll
    for (int it = 0; it < 16; ++it) {
        int i   = t + it * 512;
        int mat = i >> 10;
        int l   = mat & 3;
        int e   = (i & 1023) << 2;
        int k   = e >> 6, n0 = e & 63;
        int km  = (k == 63) ? 0 : k;          // k % 63
        float vals[4] = {wv[it].x, wv[it].y, wv[it].z, wv[it].w};
        #pragma unroll
        for (int q = 0; q < 4; ++q) {
            int nn = n0 + q;
            int nm = (nn == 63) ? 0 : nn;
            bool keep = (l == 0) ? (k <= nm)
                      : (l == 3) ? (km < nn)
                                 : (km <= nm);
            if (!keep) vals[q] = 0.0f;
        }
        *(float4*)(wsm + mat * WST + k * WROW + n0) =
            make_float4(vals[0], vals[1], vals[2], vals[3]);
    }
    __syncthreads();

    float* zrow0 = zb + (p * 16 + g) * AST;
    float* zrow1 = zb + (p * 16 + g + 8) * AST;

    // Prefetch layer-0 B-fragments (mat exec order: 4,5,6,7,0,1,2,3).
    float2 Bcur[8], Bnxt[8];
    {
        const float* wb = wsm + 4 * WST + n;
        #pragma unroll
        for (int kb = 0; kb < 8; ++kb) {
            int k0 = kb * 8 + tig;
            Bcur[kb] = make_float2(wb[k0 * WROW], wb[(k0 + 4) * WROW]);
        }
    }

    // ---- 8 chained layers, fully unrolled; tile-scoped barriers.
    // Flow reversal folded into layer-4 A reads (columns 63-k) and the final
    // epilogue's swapped zbuf read; zbuf always stores u (unreversed).
    #pragma unroll
    for (int li = 0; li < 8; ++li) {
        const int l  = ((li < 4) ? (4 + li) : (li - 4)) & 3;
        const int rd = li & 1, wr = (li + 1) & 1;

        // Prefetch next layer's B-fragments (conflict-free LDS, overlaps MMAs).
        if (li < 7) {
            const int nmat = (li < 3) ? (5 + li) : (li - 3);
            const float* wb = wsm + nmat * WST + n;
            #pragma unroll
            for (int kb = 0; kb < 8; ++kb) {
                int k0 = kb * 8 + tig;
                Bnxt[kb] = make_float2(wb[k0 * WROW], wb[(k0 + 4) * WROW]);
            }
        }

        // A-fragments (conflict-free LDS; layer 4 reads reversed columns).
        const float* ar0 = actb + ((rd * 2 + p) * 16 + g) * AST;
        const float* ar1 = actb + ((rd * 2 + p) * 16 + g + 8) * AST;
        float Afr[32];
        #pragma unroll
        for (int kb = 0; kb < 8; ++kb) {
            int k0 = kb * 8 + tig, k1 = k0 + 4;
            if (li == 4) { k0 = 63 - k0; k1 = 63 - k1; }
            Afr[kb*4+0] = ar0[k0];
            Afr[kb*4+1] = ar1[k0];
            Afr[kb*4+2] = ar0[k1];
            Afr[kb*4+3] = ar1[k1];
        }

        // Dual accumulator chains, merged at the end.
        float accA[4] = {0.f, 0.f, 0.f, 0.f};
        float accB[4] = {0.f, 0.f, 0.f, 0.f};
        #pragma unroll
        for (int kb = 0; kb < 4; ++kb) mma8(accA, Afr + kb*4, Bcur[kb]);
        #pragma unroll
        for (int kb = 4; kb < 8; ++kb) mma8(accB, Afr + kb*4, Bcur[kb]);
        float acc[4];
        #pragma unroll
        for (int i = 0; i < 4; ++i) acc[i] = accA[i] + accB[i];

        const float2 bias = biasr[li];
        float* aw0 = actb + ((wr * 2 + p) * 16 + g) * AST;
        float* aw1 = actb + ((wr * 2 + p) * 16 + g + 8) * AST;

        if (l < 3) {
            float v0 = fmaxf(acc[0] + bias.x, 0.f);
            float v1 = fmaxf(acc[1] + bias.y, 0.f);
            float v2 = fmaxf(acc[2] + bias.x, 0.f);
            float v3 = fmaxf(acc[3] + bias.y, 0.f);
            *(float2*)(aw0 + c) = make_float2(v0, v1);
            *(float2*)(aw1 + c) = make_float2(v2, v3);
            tile_bar(p);
        } else if (li == 3) {
            // u = z - shift_1(z); store u unreversed (same-lane zbuf rmw).
            float2 z0 = *(const float2*)(zrow0 + c);
            float2 z1 = *(const float2*)(zrow1 + c);
            float u0 = z0.x - (acc[0] + bias.x);
            float u1 = z0.y - (acc[1] + bias.y);
            float u2 = z1.x - (acc[2] + bias.x);
            float u3 = z1.y - (acc[3] + bias.y);
            *(float2*)(aw0 + c) = make_float2(u0, u1);
            *(float2*)(aw1 + c) = make_float2(u2, u3);
            *(float2*)(zrow0 + c) = make_float2(u0, u1);
            *(float2*)(zrow1 + c) = make_float2(u2, u3);
            tile_bar(p);
        } else {
            // Final: out[c] = v[c] - shift_0(v)[c], v[c] = u[63-c].
            float2 zr0 = *(const float2*)(zrow0 + 62 - c);  // (u[62-c], u[63-c])
            float2 zr1 = *(const float2*)(zrow1 + 62 - c);
            float zn0 = zr0.y - (acc[0] + bias.x);
            float zn1 = zr0.x - (acc[1] + bias.y);
            float zn2 = zr1.y - (acc[2] + bias.x);
            float zn3 = zr1.x - (acc[3] + bias.y);
            const int r0 = rowbase + g, r1 = r0 + 8;
            if (r0 < B)
                *(float2*)(out + (size_t)r0*64 + c) = make_float2(zn0, zn1);
            if (r1 < B)
                *(float2*)(out + (size_t)r1*64 + c) = make_float2(zn2, zn3);
        }

        // Rotate prefetch buffer (register renames under full unroll).
        #pragma unroll
        for (int i = 0; i < 8; ++i) Bcur[i] = Bnxt[i];
    }
}

extern "C" void kernel_launch(void* const* d_in, const int* in_sizes, int n_in,
                              void* d_out, int out_size) {
    const float* zm = (const float*)d_in[0];
    const float* lv = (const float*)d_in[1];
    const float* ep = (const float*)d_in[2];
    const float* W0 = (const float*)d_in[3];
    const float* b0 = (const float*)d_in[4];
    const float* W1 = (const float*)d_in[5];
    const float* b1 = (const float*)d_in[6];
    const float* W2 = (const float*)d_in[7];
    const float* b2 = (const float*)d_in[8];
    const float* Wo = (const float*)d_in[9];
    const float* bo = (const float*)d_in[10];

    int B = in_sizes[0] / 64;

    int smem = (8 * WST + 2 * 2 * 16 * AST + 2 * 16 * AST) * (int)sizeof(float);
    cudaFuncSetAttribute(iaf_main, cudaFuncAttributeMaxDynamicSharedMemorySize,
                         smem);
    int grid = (B + 31) / 32;
    iaf_main<<<grid, 512, smem>>>(zm, lv, ep, W0, b0, W1, b1, W2, b2, Wo, bo,
                                  (float*)d_out, B);
}

// round 14
// speedup vs baseline: 1.2523x; 1.0923x over previous
#include <cuda_runtime.h>
#include <cuda_fp16.h>
#include <math.h>
#include <stdint.h>

// IAF, 2 MADE flows, B=4096, D=H=64.
// Identity (verified R1/R4-R13): the reference forward scan is the exact
// inverse of z -> z - shift(z), so density = -0.5*D*log(2pi) - 0.5*sum(lv)
// - 0.5*sum(eps^2); only the inverse pass (8 masked [Bx64]@[64x64] GEMMs) runs.
// R14: fp16 m16n8k16 MMA (same 10 mantissa bits as tf32 -> same accuracy,
// half the smem bytes & MMAs). Weights staged as k-packed half2 (stride 72,
// conflict-free B loads); activations half2 (stride 36, conflict-free A);
// exact z kept fp32. Structure otherwise = R13 (16 warps = 2 tiles x 8
// n-blocks, tile barriers, folded reversal, register biases, LDG-first).

#define C_DENS (-58.81206612509905f)
#define AST  68                // fp32 z row stride (floats)
#define ASTH 36                // activation row stride (half2 units)
#define NSTW 72                // weight row stride (half2 units)
#define WMAT (32 * NSTW)       // half2 per staged matrix (2304)

static __device__ __forceinline__ void mma16(float* d, uint32_t a0, uint32_t a1,
                                             uint32_t a2, uint32_t a3,
                                             uint32_t b0, uint32_t b1) {
    asm volatile(
        "mma.sync.aligned.m16n8k16.row.col.f32.f16.f16.f32 "
        "{%0,%1,%2,%3}, {%4,%5,%6,%7}, {%8,%9}, {%0,%1,%2,%3};"
        : "+f"(d[0]), "+f"(d[1]), "+f"(d[2]), "+f"(d[3])
        : "r"(a0), "r"(a1), "r"(a2), "r"(a3), "r"(b0), "r"(b1));
}

static __device__ __forceinline__ void tile_bar(int p) {
    asm volatile("bar.sync %0, 256;" :: "r"(p + 1) : "memory");
}

static __device__ __forceinline__ uint32_t h2swap(uint32_t v) {
    return __byte_perm(v, 0, 0x1032);       // swap fp16 halves
}

static __device__ __forceinline__ uint32_t f2h2(float lo, float hi) {
    __half2 h = __floats2half2_rn(lo, hi);
    return *reinterpret_cast<uint32_t*>(&h);
}

__global__ __launch_bounds__(512, 1)
void iaf_main(const float* __restrict__ zm, const float* __restrict__ lv,
              const float* __restrict__ ep,
              const float* __restrict__ W0, const float* __restrict__ b0,
              const float* __restrict__ W1, const float* __restrict__ b1,
              const float* __restrict__ W2, const float* __restrict__ b2,
              const float* __restrict__ Wo, const float* __restrict__ bo,
              float* __restrict__ out, int B)
{
    extern __shared__ float sm[];
    uint32_t* wsm2 = (uint32_t*)sm;           // [8][32 kpair][NSTW] half2 weights
    uint32_t* abuf = wsm2 + 8 * WMAT;         // [2][2][16][ASTH] half2 acts
    float*    zb   = (float*)(abuf + 2 * 2 * 16 * ASTH);  // [2][16][AST] fp32 z

    const int t = threadIdx.x;
    const int lane = t & 31, wid = t >> 5;
    const int p = wid >> 3, h = wid & 7;      // tile, n-block (8 cols)
    const int g = lane >> 2, tig = lane & 3;
    const int rowbase = blockIdx.x * 32 + p * 16;
    const int n = h * 8 + g;                  // this lane's weight column
    const int c = 8 * h + 2 * tig;            // this lane's output column pair

    // ---- Issue ALL weight LDGs first; latency overlaps init below.
    float4 wv[16];
    #pragma unroll
    for (int it = 0; it < 16; ++it) {
        int i   = t + it * 512;               // float4 granule, 0..8191
        int mat = i >> 10;
        int f = mat >> 2, l = mat & 3;
        int e = (i & 1023) << 2;
        const float* src = (l == 0) ? W0 : (l == 1) ? W1 : (l == 2) ? W2 : Wo;
        wv[it] = *(const float4*)(src + f * 4096 + e);
    }

    // Biases (fp32) for this lane's columns, all 8 layers (exec order).
    float2 biasr[8];
    {
        const float* Bseq[8] = { b0 + 64, b1 + 64, b2 + 64, bo + 64,
                                 b0,      b1,      b2,      bo      };
        #pragma unroll
        for (int i = 0; i < 8; ++i)
            biasr[i] = *(const float2*)(Bseq[i] + c);
    }

    // ---- Init: z0 = zm + exp(0.5*lv)*eps; density; acts fp16, z fp32.
    {
        int r = t >> 4, seg = t & 15;         // 32 rows x 16 col-segments
        int pi = r >> 4, ri = r & 15;
        int gr = blockIdx.x * 32 + r;
        bool v = gr < B;
        int col = seg * 4;
        const size_t go = (size_t)gr * 64 + col;
        float4 a = v ? *(const float4*)(zm + go) : make_float4(0,0,0,0);
        float4 b = v ? *(const float4*)(lv + go) : make_float4(0,0,0,0);
        float4 cc = v ? *(const float4*)(ep + go) : make_float4(0,0,0,0);
        float4 z4;
        z4.x = a.x + __expf(0.5f * b.x) * cc.x;
        z4.y = a.y + __expf(0.5f * b.y) * cc.y;
        z4.z = a.z + __expf(0.5f * b.z) * cc.z;
        z4.w = a.w + __expf(0.5f * b.w) * cc.w;
        *(float4*)(zb + (pi * 16 + ri) * AST + col) = z4;
        uint2 hp = make_uint2(f2h2(z4.x, z4.y), f2h2(z4.z, z4.w));
        *(uint2*)(abuf + ((0 * 2 + pi) * 16 + ri) * ASTH + seg * 2) = hp;
        float slv = b.x + b.y + b.z + b.w;
        float se2 = cc.x*cc.x + cc.y*cc.y + cc.z*cc.z + cc.w*cc.w;
        #pragma unroll
        for (int m = 1; m <= 8; m <<= 1) {
            slv += __shfl_xor_sync(0xffffffffu, slv, m);
            se2 += __shfl_xor_sync(0xffffffffu, se2, m);
        }
        if (seg == 0 && v)
            out[(size_t)B * 64 + gr] = C_DENS - 0.5f * slv - 0.5f * se2;
    }

    // ---- Mask + cvt fp16 + k-pack + store staged weights.
    // Within a warp: lanes 0-15 hold row k (even), lanes 16-31 row k+1, same
    // n0 columns -> shfl_down(16) pairs rows; byte_perm interleaves halves.
    // Masks (d_h[h]=h%63+1): m_in: k<=n%63; m_hid: k%63<=n%63; m_out: k%63<n.
    #pragma unroll
    for (int it = 0; it < 16; ++it) {
        int i   = t + it * 512;
        int mat = i >> 10;
        int l   = mat & 3;
        int e   = (i & 1023) << 2;
        int k   = e >> 6, n0 = e & 63;
        int km  = (k == 63) ? 0 : k;          // k % 63
        float vals[4] = {wv[it].x, wv[it].y, wv[it].z, wv[it].w};
        #pragma unroll
        for (int q = 0; q < 4; ++q) {
            int nn = n0 + q;
            int nm = (nn == 63) ? 0 : nn;
            bool keep = (l == 0) ? (k <= nm)
                      : (l == 3) ? (km < nn)
                                 : (km <= nm);
            if (!keep) vals[q] = 0.0f;
        }
        uint32_t m01 = f2h2(vals[0], vals[1]);
        uint32_t m23 = f2h2(vals[2], vals[3]);
        uint32_t o01 = __shfl_down_sync(0xffffffffu, m01, 16);
        uint32_t o23 = __shfl_down_sync(0xffffffffu, m23, 16);
        if (lane < 16) {
            uint4 r;
            r.x = __byte_perm(m01, o01, 0x5410);   // (W[k][n0],   W[k+1][n0])
            r.y = __byte_perm(m01, o01, 0x7632);   // (W[k][n0+1], W[k+1][n0+1])
            r.z = __byte_perm(m23, o23, 0x5410);
            r.w = __byte_perm(m23, o23, 0x7632);
            *(uint4*)(wsm2 + (mat * 32 + (k >> 1)) * NSTW + n0) = r;
        }
    }
    __syncthreads();

    float* zrow0 = zb + (p * 16 + g) * AST;
    float* zrow1 = zb + (p * 16 + g + 8) * AST;

    // Prefetch layer-0 B-fragments (mat exec order: 4,5,6,7,0,1,2,3).
    uint32_t Bc0[4], Bc1[4], Bn0[4], Bn1[4];
    {
        const uint32_t* wb = wsm2 + 4 * WMAT + n;
        #pragma unroll
        for (int kb = 0; kb < 4; ++kb) {
            Bc0[kb] = wb[(kb * 8 + tig) * NSTW];
            Bc1[kb] = wb[(kb * 8 + tig + 4) * NSTW];
        }
    }

    // ---- 8 chained layers, fully unrolled; tile-scoped barriers.
    // Flow reversal folded into layer-4 A reads (swapped-half reversed pairs)
    // and the final epilogue's swapped zbuf read; zbuf stores u unreversed.
    #pragma unroll
    for (int li = 0; li < 8; ++li) {
        const int l  = ((li < 4) ? (4 + li) : (li - 4)) & 3;
        const int rd = li & 1, wr = (li + 1) & 1;

        // Prefetch next layer's B-fragments (conflict-free, overlaps MMAs).
        if (li < 7) {
            const int nmat = (li < 3) ? (5 + li) : (li - 3);
            const uint32_t* wb = wsm2 + nmat * WMAT + n;
            #pragma unroll
            for (int kb = 0; kb < 4; ++kb) {
                Bn0[kb] = wb[(kb * 8 + tig) * NSTW];
                Bn1[kb] = wb[(kb * 8 + tig + 4) * NSTW];
            }
        }

        // A-fragments (conflict-free LDS; layer 4 = reversed swapped pairs).
        const uint32_t* ar0 = abuf + ((rd * 2 + p) * 16 + g) * ASTH;
        const uint32_t* ar1 = ar0 + 8 * ASTH;
        uint32_t A0[4], A1[4], A2[4], A3[4];
        #pragma unroll
        for (int kb = 0; kb < 4; ++kb) {
            if (li == 4) {
                int j0 = 31 - kb * 8 - tig, j2 = j0 - 4;
                A0[kb] = h2swap(ar0[j0]);
                A1[kb] = h2swap(ar1[j0]);
                A2[kb] = h2swap(ar0[j2]);
                A3[kb] = h2swap(ar1[j2]);
            } else {
                int j0 = kb * 8 + tig, j2 = j0 + 4;
                A0[kb] = ar0[j0];
                A1[kb] = ar1[j0];
                A2[kb] = ar0[j2];
                A3[kb] = ar1[j2];
            }
        }

        // Dual accumulator chains, merged at the end.
        float accA[4] = {0.f, 0.f, 0.f, 0.f};
        float accB[4] = {0.f, 0.f, 0.f, 0.f};
        mma16(accA, A0[0], A1[0], A2[0], A3[0], Bc0[0], Bc1[0]);
        mma16(accA, A0[1], A1[1], A2[1], A3[1], Bc0[1], Bc1[1]);
        mma16(accB, A0[2], A1[2], A2[2], A3[2], Bc0[2], Bc1[2]);
        mma16(accB, A0[3], A1[3], A2[3], A3[3], Bc0[3], Bc1[3]);
        float acc[4];
        #pragma unroll
        for (int i = 0; i < 4; ++i) acc[i] = accA[i] + accB[i];

        const float2 bias = biasr[li];
        uint32_t* aw0 = abuf + ((wr * 2 + p) * 16 + g) * ASTH;
        uint32_t* aw1 = aw0 + 8 * ASTH;
        const int jc = 4 * h + tig;           // half2 column of pair (c, c+1)

        if (l < 3) {
            float v0 = fmaxf(acc[0] + bias.x, 0.f);
            float v1 = fmaxf(acc[1] + bias.y, 0.f);
            float v2 = fmaxf(acc[2] + bias.x, 0.f);
            float v3 = fmaxf(acc[3] + bias.y, 0.f);
            aw0[jc] = f2h2(v0, v1);
            aw1[jc] = f2h2(v2, v3);
            tile_bar(p);
        } else if (li == 3) {
            // u = z - shift_1(z); exact fp32 to zb, fp16 to act buffer.
            float2 z0 = *(const float2*)(zrow0 + c);
            float2 z1 = *(const float2*)(zrow1 + c);
            float u0 = z0.x - (acc[0] + bias.x);
            float u1 = z0.y - (acc[1] + bias.y);
            float u2 = z1.x - (acc[2] + bias.x);
            float u3 = z1.y - (acc[3] + bias.y);
            aw0[jc] = f2h2(u0, u1);
            aw1[jc] = f2h2(u2, u3);
            *(float2*)(zrow0 + c) = make_float2(u0, u1);
            *(float2*)(zrow1 + c) = make_float2(u2, u3);
            tile_bar(p);
        } else {
            // Final: out[c] = v[c] - shift_0(v)[c], v[c] = u[63-c] (fp32 zb).
            float2 zr0 = *(const float2*)(zrow0 + 62 - c);  // (u[62-c], u[63-c])
            float2 zr1 = *(const float2*)(zrow1 + 62 - c);
            float zn0 = zr0.y - (acc[0] + bias.x);
            float zn1 = zr0.x - (acc[1] + bias.y);
            float zn2 = zr1.y - (acc[2] + bias.x);
            float zn3 = zr1.x - (acc[3] + bias.y);
            const int r0 = rowbase + g, r1 = r0 + 8;
            if (r0 < B)
                *(float2*)(out + (size_t)r0*64 + c) = make_float2(zn0, zn1);
            if (r1 < B)
                *(float2*)(out + (size_t)r1*64 + c) = make_float2(zn2, zn3);
        }

        // Rotate prefetch buffers (register renames under full unroll).
        #pragma unroll
        for (int i = 0; i < 4; ++i) { Bc0[i] = Bn0[i]; Bc1[i] = Bn1[i]; }
    }
}

extern "C" void kernel_launch(void* const* d_in, const int* in_sizes, int n_in,
                              void* d_out, int out_size) {
    const float* zm = (const float*)d_in[0];
    const float* lv = (const float*)d_in[1];
    const float* ep = (const float*)d_in[2];
    const float* W0 = (const float*)d_in[3];
    const float* b0 = (const float*)d_in[4];
    const float* W1 = (const float*)d_in[5];
    const float* b1 = (const float*)d_in[6];
    const float* W2 = (const float*)d_in[7];
    const float* b2 = (const float*)d_in[8];
    const float* Wo = (const float*)d_in[9];
    const float* bo = (const float*)d_in[10];

    int B = in_sizes[0] / 64;

    int smem = (8 * WMAT + 2 * 2 * 16 * ASTH) * 4 + 2 * 16 * AST * 4;  // 91648
    cudaFuncSetAttribute(iaf_main, cudaFuncAttributeMaxDynamicSharedMemorySize,
                         smem);
    int grid = (B + 31) / 32;
    iaf_main<<<grid, 512, smem>>>(zm, lv, ep, W0, b0, W1, b1, W2, b2, Wo, bo,
                                  (float*)d_out, B);
}

// round 15
// speedup vs baseline: 1.2921x; 1.0317x over previous
#include <cuda_runtime.h>
#include <cuda_fp16.h>
#include <math.h>
#include <stdint.h>

// IAF, 2 MADE flows, B=4096, D=H=64.
// Identity (verified R1/R4-R14): the reference forward scan is the exact
// inverse of z -> z - shift(z), so density = -0.5*D*log(2pi) - 0.5*sum(lv)
// - 0.5*sum(eps^2); only the inverse pass (8 masked [Bx64]@[64x64] GEMMs) runs.
// R15: preamble restructured for thread-local k-pair packing (2 float4 loads
// -> 1 uint4 half2 store, no shfl/byte_perm, no idle lanes, 8 iterations).
// Mainloop frozen from R14: fp16 m16n8k16 MMA, conflict-free smem strides,
// 16 warps = 2 tiles x 8 n-blocks, tile barriers, folded reversal.

#define C_DENS (-58.81206612509905f)
#define AST  68                // fp32 z row stride (floats)
#define ASTH 36                // activation row stride (half2 units)
#define NSTW 72                // weight row stride (half2 units)
#define WMAT (32 * NSTW)       // half2 per staged matrix (2304)

static __device__ __forceinline__ void mma16(float* d, uint32_t a0, uint32_t a1,
                                             uint32_t a2, uint32_t a3,
                                             uint32_t b0, uint32_t b1) {
    asm volatile(
        "mma.sync.aligned.m16n8k16.row.col.f32.f16.f16.f32 "
        "{%0,%1,%2,%3}, {%4,%5,%6,%7}, {%8,%9}, {%0,%1,%2,%3};"
        : "+f"(d[0]), "+f"(d[1]), "+f"(d[2]), "+f"(d[3])
        : "r"(a0), "r"(a1), "r"(a2), "r"(a3), "r"(b0), "r"(b1));
}

static __device__ __forceinline__ void tile_bar(int p) {
    asm volatile("bar.sync %0, 256;" :: "r"(p + 1) : "memory");
}

static __device__ __forceinline__ uint32_t h2swap(uint32_t v) {
    return __byte_perm(v, 0, 0x1032);       // swap fp16 halves
}

static __device__ __forceinline__ uint32_t f2h2(float lo, float hi) {
    __half2 h = __floats2half2_rn(lo, hi);
    return *reinterpret_cast<uint32_t*>(&h);
}

__global__ __launch_bounds__(512, 1)
void iaf_main(const float* __restrict__ zm, const float* __restrict__ lv,
              const float* __restrict__ ep,
              const float* __restrict__ W0, const float* __restrict__ b0,
              const float* __restrict__ W1, const float* __restrict__ b1,
              const float* __restrict__ W2, const float* __restrict__ b2,
              const float* __restrict__ Wo, const float* __restrict__ bo,
              float* __restrict__ out, int B)
{
    extern __shared__ float sm[];
    uint32_t* wsm2 = (uint32_t*)sm;           // [8][32 kpair][NSTW] half2 weights
    uint32_t* abuf = wsm2 + 8 * WMAT;         // [2][2][16][ASTH] half2 acts
    float*    zb   = (float*)(abuf + 2 * 2 * 16 * ASTH);  // [2][16][AST] fp32 z

    const int t = threadIdx.x;
    const int lane = t & 31, wid = t >> 5;
    const int p = wid >> 3, h = wid & 7;      // tile, n-block (8 cols)
    const int g = lane >> 2, tig = lane & 3;
    const int rowbase = blockIdx.x * 32 + p * 16;
    const int n = h * 8 + g;                  // this lane's weight column
    const int c = 8 * h + 2 * tig;            // this lane's output column pair

    // ---- Issue ALL weight LDGs first; latency overlaps init below.
    // Iteration i = t + it*512 covers (mat, kpair kp, 4-col granule n0):
    //   mat = i>>9, kp = (i&511)>>4, n0 = (i&15)<<2.
    // Thread loads rows 2kp and 2kp+1 at cols n0..n0+3 (coalesced 256B/row).
    float4 wa[8], wb[8];
    #pragma unroll
    for (int it = 0; it < 8; ++it) {
        int i   = t + it * 512;               // 0..4095
        int mat = i >> 9;
        int f = mat >> 2, l = mat & 3;
        int rem = i & 511;
        int kp  = rem >> 4;
        int n0  = (rem & 15) << 2;
        const float* src = (l == 0) ? W0 : (l == 1) ? W1 : (l == 2) ? W2 : Wo;
        src += f * 4096 + (kp << 7) + n0;     // row 2kp
        wa[it] = *(const float4*)(src);
        wb[it] = *(const float4*)(src + 64);  // row 2kp+1
    }

    // Biases (fp32) for this lane's columns, all 8 layers (exec order).
    float2 biasr[8];
    {
        const float* Bseq[8] = { b0 + 64, b1 + 64, b2 + 64, bo + 64,
                                 b0,      b1,      b2,      bo      };
        #pragma unroll
        for (int i = 0; i < 8; ++i)
            biasr[i] = *(const float2*)(Bseq[i] + c);
    }

    // ---- Init: z0 = zm + exp(0.5*lv)*eps; density; acts fp16, z fp32.
    {
        int r = t >> 4, seg = t & 15;         // 32 rows x 16 col-segments
        int pi = r >> 4, ri = r & 15;
        int gr = blockIdx.x * 32 + r;
        bool v = gr < B;
        int col = seg * 4;
        const size_t go = (size_t)gr * 64 + col;
        float4 a = v ? *(const float4*)(zm + go) : make_float4(0,0,0,0);
        float4 b = v ? *(const float4*)(lv + go) : make_float4(0,0,0,0);
        float4 cc = v ? *(const float4*)(ep + go) : make_float4(0,0,0,0);
        float4 z4;
        z4.x = a.x + __expf(0.5f * b.x) * cc.x;
        z4.y = a.y + __expf(0.5f * b.y) * cc.y;
        z4.z = a.z + __expf(0.5f * b.z) * cc.z;
        z4.w = a.w + __expf(0.5f * b.w) * cc.w;
        *(float4*)(zb + (pi * 16 + ri) * AST + col) = z4;
        uint2 hp = make_uint2(f2h2(z4.x, z4.y), f2h2(z4.z, z4.w));
        *(uint2*)(abuf + ((0 * 2 + pi) * 16 + ri) * ASTH + seg * 2) = hp;
        float slv = b.x + b.y + b.z + b.w;
        float se2 = cc.x*cc.x + cc.y*cc.y + cc.z*cc.z + cc.w*cc.w;
        #pragma unroll
        for (int m = 1; m <= 8; m <<= 1) {
            slv += __shfl_xor_sync(0xffffffffu, slv, m);
            se2 += __shfl_xor_sync(0xffffffffu, se2, m);
        }
        if (seg == 0 && v)
            out[(size_t)B * 64 + gr] = C_DENS - 0.5f * slv - 0.5f * se2;
    }

    // ---- Mask + cvt fp16 + k-pack + store staged weights (thread-local).
    // Masks (d_h[h]=h%63+1): m_in: k<=n%63; m_hid: k%63<=n%63; m_out: k%63<n.
    // k0 = 2kp <= 62 so k0%63 == k0; k1 = 2kp+1, k1%63 = (k1==63)?0:k1.
    #pragma unroll
    for (int it = 0; it < 8; ++it) {
        int i   = t + it * 512;
        int mat = i >> 9;
        int l   = mat & 3;
        int rem = i & 511;
        int kp  = rem >> 4;
        int n0  = (rem & 15) << 2;
        int k0  = kp << 1;
        int k1  = k0 + 1;
        int k1m = (k1 == 63) ? 0 : k1;
        float va[4] = {wa[it].x, wa[it].y, wa[it].z, wa[it].w};
        float vb[4] = {wb[it].x, wb[it].y, wb[it].z, wb[it].w};
        uint4 r;
        uint32_t* rp = &r.x;
        #pragma unroll
        for (int q = 0; q < 4; ++q) {
            int nn = n0 + q;
            int nm = (nn == 63) ? 0 : nn;
            bool ka = (l == 0) ? (k0 <= nm)
                    : (l == 3) ? (k0 < nn)
                               : (k0 <= nm);
            bool kb2 = (l == 0) ? (k1 <= nm)
                     : (l == 3) ? (k1m < nn)
                                : (k1m <= nm);
            rp[q] = f2h2(ka ? va[q] : 0.0f, kb2 ? vb[q] : 0.0f);
        }
        *(uint4*)(wsm2 + (mat * 32 + kp) * NSTW + n0) = r;
    }
    __syncthreads();

    float* zrow0 = zb + (p * 16 + g) * AST;
    float* zrow1 = zb + (p * 16 + g + 8) * AST;

    // Prefetch layer-0 B-fragments (mat exec order: 4,5,6,7,0,1,2,3).
    uint32_t Bc0[4], Bc1[4], Bn0[4], Bn1[4];
    {
        const uint32_t* wbp = wsm2 + 4 * WMAT + n;
        #pragma unroll
        for (int kb = 0; kb < 4; ++kb) {
            Bc0[kb] = wbp[(kb * 8 + tig) * NSTW];
            Bc1[kb] = wbp[(kb * 8 + tig + 4) * NSTW];
        }
    }

    // ---- 8 chained layers, fully unrolled; tile-scoped barriers.
    // Flow reversal folded into layer-4 A reads (swapped-half reversed pairs)
    // and the final epilogue's swapped zbuf read; zbuf stores u unreversed.
    #pragma unroll
    for (int li = 0; li < 8; ++li) {
        const int l  = ((li < 4) ? (4 + li) : (li - 4)) & 3;
        const int rd = li & 1, wr = (li + 1) & 1;

        // Prefetch next layer's B-fragments (conflict-free, overlaps MMAs).
        if (li < 7) {
            const int nmat = (li < 3) ? (5 + li) : (li - 3);
            const uint32_t* wbp = wsm2 + nmat * WMAT + n;
            #pragma unroll
            for (int kb = 0; kb < 4; ++kb) {
                Bn0[kb] = wbp[(kb * 8 + tig) * NSTW];
                Bn1[kb] = wbp[(kb * 8 + tig + 4) * NSTW];
            }
        }

        // A-fragments (conflict-free LDS; layer 4 = reversed swapped pairs).
        const uint32_t* ar0 = abuf + ((rd * 2 + p) * 16 + g) * ASTH;
        const uint32_t* ar1 = ar0 + 8 * ASTH;
        uint32_t A0[4], A1[4], A2[4], A3[4];
        #pragma unroll
        for (int kb = 0; kb < 4; ++kb) {
            if (li == 4) {
                int j0 = 31 - kb * 8 - tig, j2 = j0 - 4;
                A0[kb] = h2swap(ar0[j0]);
                A1[kb] = h2swap(ar1[j0]);
                A2[kb] = h2swap(ar0[j2]);
                A3[kb] = h2swap(ar1[j2]);
            } else {
                int j0 = kb * 8 + tig, j2 = j0 + 4;
                A0[kb] = ar0[j0];
                A1[kb] = ar1[j0];
                A2[kb] = ar0[j2];
                A3[kb] = ar1[j2];
            }
        }

        // Dual accumulator chains, merged at the end.
        float accA[4] = {0.f, 0.f, 0.f, 0.f};
        float accB[4] = {0.f, 0.f, 0.f, 0.f};
        mma16(accA, A0[0], A1[0], A2[0], A3[0], Bc0[0], Bc1[0]);
        mma16(accA, A0[1], A1[1], A2[1], A3[1], Bc0[1], Bc1[1]);
        mma16(accB, A0[2], A1[2], A2[2], A3[2], Bc0[2], Bc1[2]);
        mma16(accB, A0[3], A1[3], A2[3], A3[3], Bc0[3], Bc1[3]);
        float acc[4];
        #pragma unroll
        for (int i = 0; i < 4; ++i) acc[i] = accA[i] + accB[i];

        const float2 bias = biasr[li];
        uint32_t* aw0 = abuf + ((wr * 2 + p) * 16 + g) * ASTH;
        uint32_t* aw1 = aw0 + 8 * ASTH;
        const int jc = 4 * h + tig;           // half2 column of pair (c, c+1)

        if (l < 3) {
            float v0 = fmaxf(acc[0] + bias.x, 0.f);
            float v1 = fmaxf(acc[1] + bias.y, 0.f);
            float v2 = fmaxf(acc[2] + bias.x, 0.f);
            float v3 = fmaxf(acc[3] + bias.y, 0.f);
            aw0[jc] = f2h2(v0, v1);
            aw1[jc] = f2h2(v2, v3);
            tile_bar(p);
        } else if (li == 3) {
            // u = z - shift_1(z); exact fp32 to zb, fp16 to act buffer.
            float2 z0 = *(const float2*)(zrow0 + c);
            float2 z1 = *(const float2*)(zrow1 + c);
            float u0 = z0.x - (acc[0] + bias.x);
            float u1 = z0.y - (acc[1] + bias.y);
            float u2 = z1.x - (acc[2] + bias.x);
            float u3 = z1.y - (acc[3] + bias.y);
            aw0[jc] = f2h2(u0, u1);
            aw1[jc] = f2h2(u2, u3);
            *(float2*)(zrow0 + c) = make_float2(u0, u1);
            *(float2*)(zrow1 + c) = make_float2(u2, u3);
            tile_bar(p);
        } else {
            // Final: out[c] = v[c] - shift_0(v)[c], v[c] = u[63-c] (fp32 zb).
            float2 zr0 = *(const float2*)(zrow0 + 62 - c);  // (u[62-c], u[63-c])
            float2 zr1 = *(const float2*)(zrow1 + 62 - c);
            float zn0 = zr0.y - (acc[0] + bias.x);
            float zn1 = zr0.x - (acc[1] + bias.y);
            float zn2 = zr1.y - (acc[2] + bias.x);
            float zn3 = zr1.x - (acc[3] + bias.y);
            const int r0 = rowbase + g, r1 = r0 + 8;
            if (r0 < B)
                *(float2*)(out + (size_t)r0*64 + c) = make_float2(zn0, zn1);
            if (r1 < B)
                *(float2*)(out + (size_t)r1*64 + c) = make_float2(zn2, zn3);
        }

        // Rotate prefetch buffers (register renames under full unroll).
        #pragma unroll
        for (int i = 0; i < 4; ++i) { Bc0[i] = Bn0[i]; Bc1[i] = Bn1[i]; }
    }
}

extern "C" void kernel_launch(void* const* d_in, const int* in_sizes, int n_in,
                              void* d_out, int out_size) {
    const float* zm = (const float*)d_in[0];
    const float* lv = (const float*)d_in[1];
    const float* ep = (const float*)d_in[2];
    const float* W0 = (const float*)d_in[3];
    const float* b0 = (const float*)d_in[4];
    const float* W1 = (const float*)d_in[5];
    const float* b1 = (const float*)d_in[6];
    const float* W2 = (const float*)d_in[7];
    const float* b2 = (const float*)d_in[8];
    const float* Wo = (const float*)d_in[9];
    const float* bo = (const float*)d_in[10];

    int B = in_sizes[0] / 64;

    int smem = (8 * WMAT + 2 * 2 * 16 * ASTH) * 4 + 2 * 16 * AST * 4;  // 91648
    cudaFuncSetAttribute(iaf_main, cudaFuncAttributeMaxDynamicSharedMemorySize,
                         smem);
    int grid = (B + 31) / 32;
    iaf_main<<<grid, 512, smem>>>(zm, lv, ep, W0, b0, W1, b1, W2, b2, Wo, bo,
                                  (float*)d_out, B);
}